// round 1
// baseline (speedup 1.0000x reference)
#include <cuda_runtime.h>

// out[i] = in[i,0]*w + in[i,1]*(1-w)  ==  in[i,1] + w*(in[i,0]-in[i,1])
// N = 16777216, in: [N,2] f32, weight: [1,1] f32, out: [N,1] f32.
// Memory-bound streaming kernel: 12 B traffic per element.

__global__ __launch_bounds__(256)
void skip_kernel(const float4* __restrict__ in,
                 const float* __restrict__ w_ptr,
                 float4* __restrict__ out)
{
    const unsigned i = blockIdx.x * blockDim.x + threadIdx.x;
    const float w = __ldg(w_ptr);

    // Each thread: 4 output elements = 8 input floats = two float4 loads.
    float4 a = __ldg(&in[2u * i]);
    float4 b = __ldg(&in[2u * i + 1u]);

    float4 o;
    o.x = fmaf(w, a.x - a.y, a.y);
    o.y = fmaf(w, a.z - a.w, a.w);
    o.z = fmaf(w, b.x - b.y, b.y);
    o.w = fmaf(w, b.z - b.w, b.w);

    out[i] = o;
}

extern "C" void kernel_launch(void* const* d_in, const int* in_sizes, int n_in,
                              void* d_out, int out_size)
{
    const float* input  = (const float*)d_in[0];   // [N,2]
    const float* weight = (const float*)d_in[1];   // [1,1]
    float*       out    = (float*)d_out;           // [N,1]

    const int n = in_sizes[0] / 2;     // 16777216 outputs
    const int n4 = n / 4;              // 4 outputs per thread (N is pow2, no tail)
    const int threads = 256;
    const int blocks = n4 / threads;   // 16384

    skip_kernel<<<blocks, threads>>>((const float4*)input, weight, (float4*)out);
}